// round 3
// baseline (speedup 1.0000x reference)
#include <cuda_runtime.h>

#define N_NODES   1000000
#define N_EDGES   2000000
#define N_GRAPHS  50000
#define X_DIM     5
#define HIDDEN    110
#define G_DIM     5
#define BN_EPS    1e-5f

#define STATS_BLOCKS 592
#define CAP 1024          // main-kernel smem graph-aggregation capacity

// ---------------- device scratch (zero-initialized at load) ----------------
__device__ float g_msg[N_NODES];            // zeroed by main_kernel after use
__device__ float g_part[STATS_BLOCKS][12];  // per-block stat partials (overwritten)

struct Consts {
    float A[5][5];    // diag(s_x) @ (W_gnn @ W1)
    float cvec[5];    // t_x @ M1 + b_gnn @ W1 + b1
    float we1[5];     // W_e @ W1
    float W2[5][5];
    float b2[5];
    float s_e, t_e;   // folded edge BN affine
};
__device__ Consts g_c;

// ---------------- kernel 1: BN stats (per-block partials) + zero out ----------------
__global__ void stats_kernel(const float* __restrict__ x,
                             const float* __restrict__ ea,
                             float* __restrict__ out) {
    int tid0   = blockIdx.x * blockDim.x + threadIdx.x;
    int stride = gridDim.x * blockDim.x;

    // zero the pooled output (atomics accumulate into it later)
    float4* o4 = (float4*)out;
    const float4 z4 = make_float4(0.f, 0.f, 0.f, 0.f);
    for (int i = tid0; i < (N_GRAPHS * G_DIM) / 4; i += stride) o4[i] = z4;

    float sx[5]  = {0.f, 0.f, 0.f, 0.f, 0.f};
    float sx2[5] = {0.f, 0.f, 0.f, 0.f, 0.f};

    // x: 4 nodes (= 5 float4) per unit; channel = (u*4+t) % 5 is compile-time
    const float4* x4 = (const float4*)x;
    for (int q = tid0; q < N_NODES / 4; q += stride) {
        const float4* p = x4 + q * 5;
#pragma unroll
        for (int u = 0; u < 5; u++) {
            float4 v = p[u];
            float a0 = v.x, a1 = v.y, a2 = v.z, a3 = v.w;
            int c0 = (u * 4 + 0) % 5, c1 = (u * 4 + 1) % 5;
            int c2 = (u * 4 + 2) % 5, c3 = (u * 4 + 3) % 5;
            sx[c0] += a0; sx2[c0] += a0 * a0;
            sx[c1] += a1; sx2[c1] += a1 * a1;
            sx[c2] += a2; sx2[c2] += a2 * a2;
            sx[c3] += a3; sx2[c3] += a3 * a3;
        }
    }

    float se = 0.f, se2 = 0.f;
    const float4* e4 = (const float4*)ea;
    for (int i = tid0; i < N_EDGES / 4; i += stride) {
        float4 v = e4[i];
        se  += v.x + v.y + v.z + v.w;
        se2 += v.x * v.x + v.y * v.y + v.z * v.z + v.w * v.w;
    }

    // warp reduce 12 partials
#pragma unroll
    for (int off = 16; off > 0; off >>= 1) {
#pragma unroll
        for (int j = 0; j < 5; j++) {
            sx[j]  += __shfl_down_sync(0xffffffffu, sx[j],  off);
            sx2[j] += __shfl_down_sync(0xffffffffu, sx2[j], off);
        }
        se  += __shfl_down_sync(0xffffffffu, se,  off);
        se2 += __shfl_down_sync(0xffffffffu, se2, off);
    }

    __shared__ float red[12][8];
    int w = threadIdx.x >> 5, l = threadIdx.x & 31;
    if (l == 0) {
#pragma unroll
        for (int j = 0; j < 5; j++) { red[j][w] = sx[j]; red[5 + j][w] = sx2[j]; }
        red[10][w] = se; red[11][w] = se2;
    }
    __syncthreads();
    if (threadIdx.x < 12) {
        float a = 0.f;
        int nw = blockDim.x >> 5;
        for (int k = 0; k < nw; k++) a += red[threadIdx.x][k];
        g_part[blockIdx.x][threadIdx.x] = a;   // plain store, no pre-zero needed
    }
}

// ---------------- kernel 2: fold everything into tiny per-node affine ----------------
__global__ void consts_kernel(const float* __restrict__ W_gnn,
                              const float* __restrict__ b_gnn,
                              const float* __restrict__ W_e,
                              const float* __restrict__ W1,
                              const float* __restrict__ b1,
                              const float* __restrict__ W2,
                              const float* __restrict__ b2,
                              const float* __restrict__ bn_x_g,
                              const float* __restrict__ bn_x_b,
                              const float* __restrict__ bn_e_g,
                              const float* __restrict__ bn_e_b) {
    __shared__ double s_red[12];
    __shared__ float  s_out[35];
    int tid  = threadIdx.x;
    int warp = tid >> 5, lane = tid & 31;

    // Phase A: reduce per-block stat partials (warps 0..11, one value each)
    if (warp < 12) {
        double acc = 0.0;
        for (int i = lane; i < STATS_BLOCKS; i += 32)
            acc += (double)g_part[i][warp];
#pragma unroll
        for (int off = 16; off > 0; off >>= 1)
            acc += __shfl_down_sync(0xffffffffu, acc, off);
        if (lane == 0) s_red[warp] = acc;
    }

    // Phase B: 35 dot products over HIDDEN, one warp each
    for (int o = warp; o < 35; o += 32) {
        const float* src;
        int g;
        if (o < 25)      { src = W_gnn + (o / 5) * HIDDEN; g = o % 5; }
        else if (o < 30) { src = W_e;                      g = o - 25; }
        else             { src = b_gnn;                    g = o - 30; }
        float acc = 0.f;
        for (int k = lane; k < HIDDEN; k += 32)
            acc += src[k] * W1[k * 5 + g];
#pragma unroll
        for (int off = 16; off > 0; off >>= 1)
            acc += __shfl_down_sync(0xffffffffu, acc, off);
        if (lane == 0) s_out[o] = acc;
    }
    __syncthreads();

    if (tid == 0) {
        float s_x[5], t_x[5];
#pragma unroll
        for (int j = 0; j < 5; j++) {
            double mu  = s_red[j] / (double)N_NODES;
            double var = s_red[5 + j] / (double)N_NODES - mu * mu;
            float  s   = bn_x_g[j] * rsqrtf((float)var + BN_EPS);
            s_x[j] = s;
            t_x[j] = bn_x_b[j] - (float)mu * s;
        }
#pragma unroll
        for (int j = 0; j < 5; j++)
#pragma unroll
            for (int g = 0; g < 5; g++)
                g_c.A[j][g] = s_x[j] * s_out[j * 5 + g];
#pragma unroll
        for (int g = 0; g < 5; g++) {
            float c = s_out[30 + g] + b1[g];
#pragma unroll
            for (int j = 0; j < 5; j++) c += t_x[j] * s_out[j * 5 + g];
            g_c.cvec[g] = c;
            g_c.we1[g]  = s_out[25 + g];
            g_c.b2[g]   = b2[g];
#pragma unroll
            for (int g2 = 0; g2 < 5; g2++) g_c.W2[g][g2] = W2[g * 5 + g2];
        }
        double mue  = s_red[10] / (double)N_EDGES;
        double vare = s_red[11] / (double)N_EDGES - mue * mue;
        float  se   = bn_e_g[0] * rsqrtf((float)vare + BN_EPS);
        g_c.s_e = se;
        g_c.t_e = bn_e_b[0] - (float)mue * se;
    }
}

// ---------------- kernel 3: scatter normalized edge messages (4 edges/thread) ----------------
__global__ void scatter_kernel(const float* __restrict__ ea,
                               const int*   __restrict__ dst) {
    int i = blockIdx.x * blockDim.x + threadIdx.x;
    if (i < N_EDGES / 4) {
        float s = g_c.s_e, t = g_c.t_e;
        float4 e = ((const float4*)ea)[i];
        int4   d = ((const int4*)dst)[i];
        atomicAdd(&g_msg[d.x], fmaf(s, e.x, t));
        atomicAdd(&g_msg[d.y], fmaf(s, e.y, t));
        atomicAdd(&g_msg[d.z], fmaf(s, e.z, t));
        atomicAdd(&g_msg[d.w], fmaf(s, e.w, t));
    }
}

// ---------------- kernel 4: per-node affine->swish->affine + pooled reduction ----------------
__global__ void __launch_bounds__(256) main_kernel(const float* __restrict__ x,
                                                   const int*   __restrict__ batch,
                                                   float* __restrict__ out) {
    __shared__ Consts c;
    __shared__ float  agg[CAP * 5];
    __shared__ int    s_bfirst, s_span;
    {
        const float* src = (const float*)&g_c;
        float* dstp = (float*)&c;
        for (int i = threadIdx.x; i < (int)(sizeof(Consts) / 4); i += blockDim.x)
            dstp[i] = src[i];
    }
    int base = blockIdx.x * blockDim.x;
    if (threadIdx.x == 0) {
        int bf = batch[base];
        int last = min(base + (int)blockDim.x, N_NODES) - 1;
        s_bfirst = bf;
        s_span   = batch[last] - bf;
    }
    __syncthreads();
    int bf = s_bfirst, span = s_span;
    bool smem_path = (span < CAP);

    if (smem_path) {
        for (int i = threadIdx.x; i < (span + 1) * 5; i += blockDim.x) agg[i] = 0.f;
    }

    int n = base + threadIdx.x;
    float o[5] = {0.f, 0.f, 0.f, 0.f, 0.f};
    int b = -1;

    if (n < N_NODES) {
        float m = g_msg[n];
        g_msg[n] = 0.f;                       // reset for next graph replay
        float p[5];
#pragma unroll
        for (int g = 0; g < 5; g++) p[g] = fmaf(m, c.we1[g], c.cvec[g]);
#pragma unroll
        for (int j = 0; j < 5; j++) {
            float xv = x[n * 5 + j];
#pragma unroll
            for (int g = 0; g < 5; g++) p[g] = fmaf(xv, c.A[j][g], p[g]);
        }
#pragma unroll
        for (int g = 0; g < 5; g++) {
            float q = p[g] / (1.f + __expf(-p[g]));   // swish
#pragma unroll
            for (int g2 = 0; g2 < 5; g2++) o[g2] = fmaf(q, c.W2[g][g2], o[g2]);
        }
#pragma unroll
        for (int g2 = 0; g2 < 5; g2++) o[g2] += c.b2[g2];
        b = batch[n];
    }
    if (smem_path) __syncthreads();           // agg zeroing done

    // warp-level segmented sum over sorted batch ids
    const unsigned FULL = 0xffffffffu;
    int lane = threadIdx.x & 31;
#pragma unroll
    for (int off = 1; off < 32; off <<= 1) {
        int   bo = __shfl_up_sync(FULL, b, off);
        float t0 = __shfl_up_sync(FULL, o[0], off);
        float t1 = __shfl_up_sync(FULL, o[1], off);
        float t2 = __shfl_up_sync(FULL, o[2], off);
        float t3 = __shfl_up_sync(FULL, o[3], off);
        float t4 = __shfl_up_sync(FULL, o[4], off);
        if (lane >= off && bo == b) {
            o[0] += t0; o[1] += t1; o[2] += t2; o[3] += t3; o[4] += t4;
        }
    }
    int bnext = __shfl_down_sync(FULL, b, 1);
    bool tail = (lane == 31) || (bnext != b);

    if (tail && n < N_NODES) {
        if (smem_path) {
            float* a = agg + (b - bf) * 5;
            atomicAdd(&a[0], o[0]); atomicAdd(&a[1], o[1]); atomicAdd(&a[2], o[2]);
            atomicAdd(&a[3], o[3]); atomicAdd(&a[4], o[4]);
        } else {
            float* op = out + b * 5;
            atomicAdd(&op[0], o[0]); atomicAdd(&op[1], o[1]); atomicAdd(&op[2], o[2]);
            atomicAdd(&op[3], o[3]); atomicAdd(&op[4], o[4]);
        }
    }

    if (smem_path) {
        __syncthreads();
        // interior graphs are exclusively owned by this block (batch sorted) -> plain store;
        // only the block's first/last graph ids can overlap neighbors -> global atomic.
        for (int idx = threadIdx.x; idx < (span + 1) * 5; idx += blockDim.x) {
            int lg = idx / 5, ch = idx % 5;
            float v = agg[idx];
            int g = bf + lg;
            if (lg == 0 || lg == span) {
                if (v != 0.f) atomicAdd(&out[g * 5 + ch], v);
            } else {
                out[g * 5 + ch] = v;
            }
        }
    }
}

// ---------------- launch ----------------
extern "C" void kernel_launch(void* const* d_in, const int* in_sizes, int n_in,
                              void* d_out, int out_size) {
    const float* x      = (const float*)d_in[0];
    const float* ea     = (const float*)d_in[1];
    const int*   batch  = (const int*)  d_in[2];
    const int*   eidx   = (const int*)  d_in[3];
    const float* bn_x_g = (const float*)d_in[4];
    const float* bn_x_b = (const float*)d_in[5];
    const float* bn_e_g = (const float*)d_in[6];
    const float* bn_e_b = (const float*)d_in[7];
    const float* W_gnn  = (const float*)d_in[8];
    const float* b_gnn  = (const float*)d_in[9];
    const float* W_e    = (const float*)d_in[10];
    const float* W1     = (const float*)d_in[11];
    const float* b1     = (const float*)d_in[12];
    const float* W2     = (const float*)d_in[13];
    const float* b2     = (const float*)d_in[14];
    float* out = (float*)d_out;

    stats_kernel<<<STATS_BLOCKS, 256>>>(x, ea, out);
    consts_kernel<<<1, 1024>>>(W_gnn, b_gnn, W_e, W1, b1, W2, b2,
                               bn_x_g, bn_x_b, bn_e_g, bn_e_b);
    scatter_kernel<<<(N_EDGES / 4 + 255) / 256, 256>>>(ea, eidx + N_EDGES);
    main_kernel<<<(N_NODES + 255) / 256, 256>>>(x, batch, out);
}

// round 4
// speedup vs baseline: 1.0259x; 1.0259x over previous
#include <cuda_runtime.h>
#include <limits.h>

#define N_NODES   1000000
#define N_EDGES   2000000
#define N_GRAPHS  50000
#define X_DIM     5
#define HIDDEN    110
#define G_DIM     5
#define BN_EPS    1e-5f

#define STATS_BLOCKS 592
#define NODES_PER_BLOCK 512   // 256 threads x 2 nodes

// ---------------- device scratch (zero-initialized at load) ----------------
__device__ float g_msg[N_NODES];            // zeroed by main_kernel after use
__device__ float g_part[STATS_BLOCKS][12];  // per-block stat partials (overwritten)

struct Consts {
    float A[5][5];    // diag(s_x) @ (W_gnn @ W1)
    float cvec[5];    // t_x @ M1 + b_gnn @ W1 + b1
    float we1[5];     // W_e @ W1
    float W2[5][5];
    float b2[5];
    float s_e, t_e;   // folded edge BN affine
};
__device__ Consts g_c;

// ---------------- kernel 1: BN stats (per-block partials) + zero out ----------------
__global__ void stats_kernel(const float* __restrict__ x,
                             const float* __restrict__ ea,
                             float* __restrict__ out) {
    int tid0   = blockIdx.x * blockDim.x + threadIdx.x;
    int stride = gridDim.x * blockDim.x;

    float4* o4 = (float4*)out;
    const float4 z4 = make_float4(0.f, 0.f, 0.f, 0.f);
    for (int i = tid0; i < (N_GRAPHS * G_DIM) / 4; i += stride) o4[i] = z4;

    float sx[5]  = {0.f, 0.f, 0.f, 0.f, 0.f};
    float sx2[5] = {0.f, 0.f, 0.f, 0.f, 0.f};

    const float4* x4 = (const float4*)x;
    for (int q = tid0; q < N_NODES / 4; q += stride) {
        const float4* p = x4 + q * 5;
#pragma unroll
        for (int u = 0; u < 5; u++) {
            float4 v = p[u];
            float a0 = v.x, a1 = v.y, a2 = v.z, a3 = v.w;
            int c0 = (u * 4 + 0) % 5, c1 = (u * 4 + 1) % 5;
            int c2 = (u * 4 + 2) % 5, c3 = (u * 4 + 3) % 5;
            sx[c0] += a0; sx2[c0] += a0 * a0;
            sx[c1] += a1; sx2[c1] += a1 * a1;
            sx[c2] += a2; sx2[c2] += a2 * a2;
            sx[c3] += a3; sx2[c3] += a3 * a3;
        }
    }

    float se = 0.f, se2 = 0.f;
    const float4* e4 = (const float4*)ea;
    for (int i = tid0; i < N_EDGES / 4; i += stride) {
        float4 v = e4[i];
        se  += v.x + v.y + v.z + v.w;
        se2 += v.x * v.x + v.y * v.y + v.z * v.z + v.w * v.w;
    }

#pragma unroll
    for (int off = 16; off > 0; off >>= 1) {
#pragma unroll
        for (int j = 0; j < 5; j++) {
            sx[j]  += __shfl_down_sync(0xffffffffu, sx[j],  off);
            sx2[j] += __shfl_down_sync(0xffffffffu, sx2[j], off);
        }
        se  += __shfl_down_sync(0xffffffffu, se,  off);
        se2 += __shfl_down_sync(0xffffffffu, se2, off);
    }

    __shared__ float red[12][8];
    int w = threadIdx.x >> 5, l = threadIdx.x & 31;
    if (l == 0) {
#pragma unroll
        for (int j = 0; j < 5; j++) { red[j][w] = sx[j]; red[5 + j][w] = sx2[j]; }
        red[10][w] = se; red[11][w] = se2;
    }
    __syncthreads();
    if (threadIdx.x < 12) {
        float a = 0.f;
        int nw = blockDim.x >> 5;
        for (int k = 0; k < nw; k++) a += red[threadIdx.x][k];
        g_part[blockIdx.x][threadIdx.x] = a;
    }
}

// ---------------- kernel 2: fold everything into tiny per-node affine ----------------
__global__ void consts_kernel(const float* __restrict__ W_gnn,
                              const float* __restrict__ b_gnn,
                              const float* __restrict__ W_e,
                              const float* __restrict__ W1,
                              const float* __restrict__ b1,
                              const float* __restrict__ W2,
                              const float* __restrict__ b2,
                              const float* __restrict__ bn_x_g,
                              const float* __restrict__ bn_x_b,
                              const float* __restrict__ bn_e_g,
                              const float* __restrict__ bn_e_b) {
    __shared__ double s_red[12];
    __shared__ float  s_out[35];
    int tid  = threadIdx.x;
    int warp = tid >> 5, lane = tid & 31;

    if (warp < 12) {
        double acc = 0.0;
        for (int i = lane; i < STATS_BLOCKS; i += 32)
            acc += (double)g_part[i][warp];
#pragma unroll
        for (int off = 16; off > 0; off >>= 1)
            acc += __shfl_down_sync(0xffffffffu, acc, off);
        if (lane == 0) s_red[warp] = acc;
    }

    for (int o = warp; o < 35; o += 32) {
        const float* src;
        int g;
        if (o < 25)      { src = W_gnn + (o / 5) * HIDDEN; g = o % 5; }
        else if (o < 30) { src = W_e;                      g = o - 25; }
        else             { src = b_gnn;                    g = o - 30; }
        float acc = 0.f;
        for (int k = lane; k < HIDDEN; k += 32)
            acc += src[k] * W1[k * 5 + g];
#pragma unroll
        for (int off = 16; off > 0; off >>= 1)
            acc += __shfl_down_sync(0xffffffffu, acc, off);
        if (lane == 0) s_out[o] = acc;
    }
    __syncthreads();

    if (tid == 0) {
        float s_x[5], t_x[5];
#pragma unroll
        for (int j = 0; j < 5; j++) {
            double mu  = s_red[j] / (double)N_NODES;
            double var = s_red[5 + j] / (double)N_NODES - mu * mu;
            float  s   = bn_x_g[j] * rsqrtf((float)var + BN_EPS);
            s_x[j] = s;
            t_x[j] = bn_x_b[j] - (float)mu * s;
        }
#pragma unroll
        for (int j = 0; j < 5; j++)
#pragma unroll
            for (int g = 0; g < 5; g++)
                g_c.A[j][g] = s_x[j] * s_out[j * 5 + g];
#pragma unroll
        for (int g = 0; g < 5; g++) {
            float cc = s_out[30 + g] + b1[g];
#pragma unroll
            for (int j = 0; j < 5; j++) cc += t_x[j] * s_out[j * 5 + g];
            g_c.cvec[g] = cc;
            g_c.we1[g]  = s_out[25 + g];
            g_c.b2[g]   = b2[g];
#pragma unroll
            for (int g2 = 0; g2 < 5; g2++) g_c.W2[g][g2] = W2[g * 5 + g2];
        }
        double mue  = s_red[10] / (double)N_EDGES;
        double vare = s_red[11] / (double)N_EDGES - mue * mue;
        float  se   = bn_e_g[0] * rsqrtf((float)vare + BN_EPS);
        g_c.s_e = se;
        g_c.t_e = bn_e_b[0] - (float)mue * se;
    }
}

// ---------------- kernel 3: scatter normalized edge messages (4 edges/thread) ----------------
__global__ void scatter_kernel(const float* __restrict__ ea,
                               const int*   __restrict__ dst) {
    int i = blockIdx.x * blockDim.x + threadIdx.x;
    if (i < N_EDGES / 4) {
        float s = g_c.s_e, t = g_c.t_e;
        float4 e = ((const float4*)ea)[i];
        int4   d = ((const int4*)dst)[i];
        atomicAdd(&g_msg[d.x], fmaf(s, e.x, t));
        atomicAdd(&g_msg[d.y], fmaf(s, e.y, t));
        atomicAdd(&g_msg[d.z], fmaf(s, e.z, t));
        atomicAdd(&g_msg[d.w], fmaf(s, e.w, t));
    }
}

// ---------------- kernel 4: 2 nodes/thread, staged x, segmented flush ----------------
__device__ __forceinline__ void node_out(const Consts& c, const float* xv, float m,
                                         float o[5]) {
    float p[5];
#pragma unroll
    for (int g = 0; g < 5; g++) p[g] = fmaf(m, c.we1[g], c.cvec[g]);
#pragma unroll
    for (int j = 0; j < 5; j++) {
        float v = xv[j];
#pragma unroll
        for (int g = 0; g < 5; g++) p[g] = fmaf(v, c.A[j][g], p[g]);
    }
#pragma unroll
    for (int g = 0; g < 5; g++) o[g] = c.b2[g];
#pragma unroll
    for (int g = 0; g < 5; g++) {
        float q = p[g] / (1.f + __expf(-p[g]));   // swish
#pragma unroll
        for (int g2 = 0; g2 < 5; g2++) o[g2] = fmaf(q, c.W2[g][g2], o[g2]);
    }
}

__global__ void __launch_bounds__(256) main_kernel(const float* __restrict__ x,
                                                   const int*   __restrict__ batch,
                                                   float* __restrict__ out) {
    __shared__ float  sxm[NODES_PER_BLOCK * 5];   // 2560 floats = 10 KB
    __shared__ Consts c;
    {
        const float* src = (const float*)&g_c;
        float* dstp = (float*)&c;
        for (int i = threadIdx.x; i < (int)(sizeof(Consts) / 4); i += blockDim.x)
            dstp[i] = src[i];
    }

    int b0 = blockIdx.x * NODES_PER_BLOCK;
    // stage x: coalesced float4 loads
    {
        const float4* x4 = (const float4*)x;
        int gbase  = (b0 * 5) >> 2;                 // b0*5 divisible by 4
        int limit4 = (N_NODES * 5) >> 2;
        float4* s4 = (float4*)sxm;
#pragma unroll
        for (int k = threadIdx.x, u = 0; u < 3; u++, k += 256) {
            if (k < NODES_PER_BLOCK * 5 / 4) {
                int gi = gbase + k;
                s4[k] = (gi < limit4) ? x4[gi] : make_float4(0.f, 0.f, 0.f, 0.f);
            }
        }
    }
    __syncthreads();

    int t  = threadIdx.x;
    int n0 = b0 + 2 * t;               // n0 even; n0 valid => n0+1 valid (N even)
    bool valid = (n0 < N_NODES);

    int   k0 = INT_MAX, k1 = INT_MAX;
    float o0[5], o1[5];
#pragma unroll
    for (int g = 0; g < 5; g++) { o0[g] = 0.f; o1[g] = 0.f; }

    if (valid) {
        float2 m2 = *(const float2*)&g_msg[n0];
        *(float2*)&g_msg[n0] = make_float2(0.f, 0.f);     // reset for next replay
        int2 bb = *(const int2*)&batch[n0];
        k0 = bb.x; k1 = bb.y;
        node_out(c, &sxm[(2 * t) * 5],     m2.x, o0);
        node_out(c, &sxm[(2 * t + 1) * 5], m2.y, o1);
    }

    // thread-local merge: scan participant carries tail-key k1
    float v[5];
    bool split = (k0 != k1);
#pragma unroll
    for (int g = 0; g < 5; g++) v[g] = split ? o1[g] : (o0[g] + o1[g]);

    // warp inclusive segmented scan on (k1, v)
    const unsigned FULL = 0xffffffffu;
    int lane = t & 31;
#pragma unroll
    for (int off = 1; off < 32; off <<= 1) {
        int   pk = __shfl_up_sync(FULL, k1, off);
        float t0 = __shfl_up_sync(FULL, v[0], off);
        float t1 = __shfl_up_sync(FULL, v[1], off);
        float t2 = __shfl_up_sync(FULL, v[2], off);
        float t3 = __shfl_up_sync(FULL, v[3], off);
        float t4 = __shfl_up_sync(FULL, v[4], off);
        if (lane >= off && pk == k1) {
            v[0] += t0; v[1] += t1; v[2] += t2; v[3] += t3; v[4] += t4;
        }
    }

    // carries for the split head segment
    int   prevKH = __shfl_up_sync(FULL, k1, 1);
    float p0 = __shfl_up_sync(FULL, v[0], 1);
    float p1 = __shfl_up_sync(FULL, v[1], 1);
    float p2 = __shfl_up_sync(FULL, v[2], 1);
    float p3 = __shfl_up_sync(FULL, v[3], 1);
    float p4 = __shfl_up_sync(FULL, v[4], 1);
    int   nkl = __shfl_down_sync(FULL, k0, 1);

    if (valid && split) {
        // segment k0 ends inside this thread; absorb preceding run if contiguous
        float h0 = o0[0], h1 = o0[1], h2 = o0[2], h3 = o0[3], h4 = o0[4];
        if (lane > 0 && prevKH == k0) { h0 += p0; h1 += p1; h2 += p2; h3 += p3; h4 += p4; }
        float* op = out + k0 * 5;
        atomicAdd(&op[0], h0); atomicAdd(&op[1], h1); atomicAdd(&op[2], h2);
        atomicAdd(&op[3], h3); atomicAdd(&op[4], h4);
    }

    // tail flush: segment k1 ends at this lane if next thread starts a new key
    bool flushTail = valid && ((lane == 31) || (nkl != k1));
    if (flushTail) {
        float* op = out + k1 * 5;
        atomicAdd(&op[0], v[0]); atomicAdd(&op[1], v[1]); atomicAdd(&op[2], v[2]);
        atomicAdd(&op[3], v[3]); atomicAdd(&op[4], v[4]);
    }
}

// ---------------- launch ----------------
extern "C" void kernel_launch(void* const* d_in, const int* in_sizes, int n_in,
                              void* d_out, int out_size) {
    const float* x      = (const float*)d_in[0];
    const float* ea     = (const float*)d_in[1];
    const int*   batch  = (const int*)  d_in[2];
    const int*   eidx   = (const int*)  d_in[3];
    const float* bn_x_g = (const float*)d_in[4];
    const float* bn_x_b = (const float*)d_in[5];
    const float* bn_e_g = (const float*)d_in[6];
    const float* bn_e_b = (const float*)d_in[7];
    const float* W_gnn  = (const float*)d_in[8];
    const float* b_gnn  = (const float*)d_in[9];
    const float* W_e    = (const float*)d_in[10];
    const float* W1     = (const float*)d_in[11];
    const float* b1     = (const float*)d_in[12];
    const float* W2     = (const float*)d_in[13];
    const float* b2     = (const float*)d_in[14];
    float* out = (float*)d_out;

    stats_kernel<<<STATS_BLOCKS, 256>>>(x, ea, out);
    consts_kernel<<<1, 1024>>>(W_gnn, b_gnn, W_e, W1, b1, W2, b2,
                               bn_x_g, bn_x_b, bn_e_g, bn_e_b);
    scatter_kernel<<<(N_EDGES / 4 + 255) / 256, 256>>>(ea, eidx + N_EDGES);
    main_kernel<<<(N_NODES + NODES_PER_BLOCK - 1) / NODES_PER_BLOCK, 256>>>(x, batch, out);
}